// round 17
// baseline (speedup 1.0000x reference)
#include <cuda_runtime.h>
#include <math.h>

// Fixed shapes per reference
#define N_PTS 262144
#define B_ 4
#define T_ 4
#define P_ 512
#define R_ 256
#define C_ 64
#define H_ 512
#define W_ 512
#define HW_ (H_ * W_)
#define RC_ (R_ * C_)
#define PRC_ (P_ * RC_)

#define COPY_BLOCKS 16384
#define SCATTER_BLOCKS (N_PTS / 16)        // 16384: 16 points per 256-thr block
#define MAIN_BLOCKS (COPY_BLOCKS + SCATTER_BLOCKS)   // 32768
#define EPI_BLOCKS 512
#define SCRATCH_ELEMS (B_ * H_ * T_ * C_)  // 524288 floats (2MB)

// Privatized accumulator [b][y][t][c] (channel-contiguous -> coalesced REDs).
// BSS zero-init; epilogue re-zeros after consuming (invariant across replays).
__device__ float g_scratch[SCRATCH_ELEMS];
__device__ unsigned int g_done;      // scatter blocks completed
__device__ unsigned int g_epi_done;  // epilogue blocks completed (reset logic)

__device__ __forceinline__ void red_add_v4(float* p, float4 v) {
    asm volatile("red.global.add.v4.f32 [%0], {%1,%2,%3,%4};"
                 :: "l"(p), "f"(v.x), "f"(v.y), "f"(v.z), "f"(v.w)
                 : "memory");
}

// Streaming 32B copy with L2 evict_first (zero-reuse stream; keep L2 for the
// pview gather working set). ptxas requires .v4.b64 width for the modifier.
__device__ __forceinline__ ulonglong4 ld_stream32(const ulonglong4* p) {
    ulonglong4 v;
    asm volatile("ld.global.nc.L2::evict_first.v4.b64 {%0,%1,%2,%3}, [%4];"
                 : "=l"(v.x), "=l"(v.y), "=l"(v.z), "=l"(v.w) : "l"(p));
    return v;
}
__device__ __forceinline__ void st_stream32(ulonglong4* p, ulonglong4 v) {
    asm volatile("st.global.L2::evict_first.v4.b64 [%0], {%1,%2,%3,%4};"
                 :: "l"(p), "l"(v.x), "l"(v.y), "l"(v.z), "l"(v.w)
                 : "memory");
}

// Parity-interleaved fused kernel (copy/scatter, proven structure) PLUS 512
// tail epilogue blocks. Tail blocks are dispatched last, so they occupy the
// draining-tail SM slots, wait for all scatter blocks (g_done), then run the
// transpose-add overlapped with the last copy waves — removing the separate
// epilogue kernel's launch + serialization.
__global__ void __launch_bounds__(256) pp_fused_kernel(
    const int4*  __restrict__ coords,
    const float* __restrict__ pview,
    const ulonglong4* __restrict__ spatial32,
    ulonglong4* __restrict__ out32)
{
    const int tid = threadIdx.x;
    const unsigned bid = blockIdx.x;

    if (bid < MAIN_BLOCKS) {
        if ((bid & 1) == 0) {
            // ---- copy path: 256MB out = spatial, 32B chunks, L2-bypassing --
            int idx = (bid >> 1) * 256 + tid;
            const int stride = COPY_BLOCKS * 256;      // 4194304
            #pragma unroll
            for (int i = 0; i < 2; i++) {
                st_stream32(out32 + idx, ld_stream32(spatial32 + idx));
                idx += stride;
            }
            return;
        }

        // ---- scatter path: 16 lanes per point, float4 per lane ----
        const int warp   = tid >> 5;
        const int half   = (tid >> 4) & 1;
        const int lane16 = tid & 15;
        const int pt = (bid >> 1) * 16 + warp * 2 + half;

        int4 c = coords[pt];
        const int b = c.x, t = c.y, yy = c.z, xx = c.w;

        // Replicate reference f32 math exactly (no FMA contraction) so the
        // xf==0 special case matches bit-for-bit.
        float yf = __fadd_rn(__fmul_rn((float)yy, 0.2f), -51.2f);
        float xf = __fadd_rn(__fmul_rn((float)xx, 0.2f), -51.2f);

        float r = sqrtf(__fadd_rn(__fmul_rn(xf, xf), __fmul_rn(yf, yf)));
        float psi;
        if (xf == 0.0f && yf >= 0.0f) {
            psi = 1.57079632679489662f;   // pi/2
        } else {
            psi = atan2f(yf, xf);
        }

        float r_idx = __fdiv_rn(r, 0.3f);
        float p_idx = __fdiv_rn(__fadd_rn(psi, 3.14159265358979323846f),
                                0.012566370614359172f);

        int r0i = (int)floorf(r_idx);
        int p0i = (int)floorf(p_idx);
        // t frac is exactly 0 -> t+1 corner weight == 0, skipped.

        const float fr = r_idx - (float)r0i;
        const float fp = p_idx - (float)p0i;

        const int r0 = r0i * C_;
        const int r1 = min(r0i + 1, R_ - 1) * C_;
        const int p0 = p0i * RC_;
        const int p1 = min(p0i + 1, P_ - 1) * RC_;

        const float4* base = (const float4*)(pview + (b * T_ + t) * PRC_) + lane16;

        float4 v00 = __ldg(base + ((p0 + r0) >> 2));
        float4 v01 = __ldg(base + ((p0 + r1) >> 2));
        float4 v10 = __ldg(base + ((p1 + r0) >> 2));
        float4 v11 = __ldg(base + ((p1 + r1) >> 2));

        const float wr0 = 1.0f - fr, wr1 = fr;
        const float wp0 = 1.0f - fp, wp1 = fp;

        float4 acc;
        acc.x = wp0 * (wr0 * v00.x + wr1 * v01.x) + wp1 * (wr0 * v10.x + wr1 * v11.x);
        acc.y = wp0 * (wr0 * v00.y + wr1 * v01.y) + wp1 * (wr0 * v10.y + wr1 * v11.y);
        acc.z = wp0 * (wr0 * v00.z + wr1 * v01.z) + wp1 * (wr0 * v10.z + wr1 * v11.z);
        acc.w = wp0 * (wr0 * v00.w + wr1 * v01.w) + wp1 * (wr0 * v10.w + wr1 * v11.w);

        float* dst = g_scratch + ((b * H_ + yy) * T_ + t) * C_ + 4 * lane16;
        red_add_v4(dst, acc);

        // Publish: this block's reds are ordered before its counter bump.
        __threadfence();
        __syncthreads();
        if (tid == 0) atomicAdd(&g_done, 1u);
        return;
    }

    // ---- epilogue tail blocks (dispatched last; overlap the copy tail) ----
    if (tid == 0) {
        while (*(volatile unsigned int*)&g_done < SCATTER_BLOCKS)
            __nanosleep(64);
    }
    __syncthreads();
    __threadfence();   // acquire: all scatter reds visible

    const int idx = (bid - MAIN_BLOCKS) * 256 + tid;   // (b, y, c) flat
    const int ch = idx & (C_ - 1);
    const int y  = (idx >> 6) & (H_ - 1);
    const int b  = idx >> 15;

    const int sbase = ((b * H_ + y) * T_) * C_ + ch;   // t stride = C_
    float v0 = g_scratch[sbase];
    float v1 = g_scratch[sbase + C_];
    float v2 = g_scratch[sbase + 2 * C_];
    float v3 = g_scratch[sbase + 3 * C_];

    g_scratch[sbase]          = 0.0f;                  // re-zero for replay
    g_scratch[sbase + C_]     = 0.0f;
    g_scratch[sbase + 2 * C_] = 0.0f;
    g_scratch[sbase + 3 * C_] = 0.0f;

    float4 v = make_float4(v0, v1, v2, v3);
    // out[b][ch][y][0..3] — 16B-aligned; fire-and-forget red (the copy path
    // already wrote these quads; red adds on top, order irrelevant since the
    // address sets {copy stores} and {epilogue reds} commute via L2 RMW).
    red_add_v4(out32 ? (float*)out32 + b * (C_ * HW_) + ch * HW_ + y * W_
                     : nullptr, v);

    // Self-reset counters (last epilogue block) for graph-replay determinism.
    __syncthreads();
    if (tid == 0) {
        unsigned int prev = atomicAdd(&g_epi_done, 1u);
        if (prev == EPI_BLOCKS - 1) {
            g_done = 0u;
            g_epi_done = 0u;
            __threadfence();
        }
    }
}

extern "C" void kernel_launch(void* const* d_in, const int* in_sizes, int n_in,
                              void* d_out, int out_size) {
    const int*   coords  = (const int*)d_in[0];   // voxel_coords [N,4] int32
    const float* pview   = (const float*)d_in[1]; // [B,T,P,R,C] f32
    const float* spatial = (const float*)d_in[2]; // [B,C,H,W] f32
    float* out = (float*)d_out;

    pp_fused_kernel<<<MAIN_BLOCKS + EPI_BLOCKS, 256>>>(
        (const int4*)coords, pview, (const ulonglong4*)spatial, (ulonglong4*)out);
}